// round 1
// baseline (speedup 1.0000x reference)
#include <cuda_runtime.h>
#include <cuda_bf16.h>
#include <cstdint>

// Problem shape (fixed by reference)
#define BATCH 32
#define CIN   64
#define HIN   128
#define WIN   128
#define COUT  128
#define HO    126
#define WO    126
#define NGRP  8
#define CPG   (COUT / NGRP)   // 16 channels per group
#define HP    63              // pooled H
#define WP    63              // pooled W
#define EPS   1e-5f

// Scratch: conv output y [B, COUT, HO, WO]  (~260 MB, static device global — allowed)
__device__ float g_y[(size_t)BATCH * COUT * HO * WO];
__device__ float g_mean[BATCH * NGRP];
__device__ float g_rstd[BATCH * NGRP];

// ---------------------------------------------------------------------------
// Kernel 1: direct conv 3x3 valid + bias -> g_y
// Block: 256 threads (16x16), each thread computes 8 Cout x (2x2 pixels).
// Tile: 32x32 output pixels, 8 output channels, one batch.
// ---------------------------------------------------------------------------
__global__ __launch_bounds__(256, 3)
void conv_kernel(const float* __restrict__ x,
                 const float* __restrict__ W,
                 const float* __restrict__ bias)
{
    __shared__ float smx[34][36];      // 34x34 input tile, padded rows
    __shared__ float smw[8][9];        // 8 cout x 9 taps for current cin

    const int tx = threadIdx.x & 15;
    const int ty = threadIdx.x >> 4;
    const int w0 = blockIdx.x * 32;
    const int h0 = blockIdx.y * 32;
    const int bz = blockIdx.z;
    const int b   = bz >> 4;           // 16 cout-blocks per batch
    const int cob = (bz & 15) * 8;

    float acc[8][4];
#pragma unroll
    for (int co = 0; co < 8; co++)
#pragma unroll
        for (int p = 0; p < 4; p++) acc[co][p] = 0.f;

    const int py = ty * 2;
    const int px = tx * 2;

    for (int ci = 0; ci < CIN; ci++) {
        // cooperative load of 34x34 input tile (zero-fill OOB)
        const float* xp = x + ((size_t)b * CIN + ci) * (HIN * WIN);
        for (int i = threadIdx.x; i < 34 * 34; i += 256) {
            int r = i / 34, c = i - r * 34;
            int hh = h0 + r, ww = w0 + c;
            float v = 0.f;
            if (hh < HIN && ww < WIN) v = xp[hh * WIN + ww];
            smx[r][c] = v;
        }
        if (threadIdx.x < 72) {
            int co = threadIdx.x / 9, k = threadIdx.x - co * 9;
            smw[co][k] = W[((size_t)(cob + co) * CIN + ci) * 9 + k];
        }
        __syncthreads();

#pragma unroll
        for (int kh = 0; kh < 3; kh++) {
#pragma unroll
            for (int kw = 0; kw < 3; kw++) {
                const float x00 = smx[py + kh][px + kw];
                const float x01 = smx[py + kh][px + kw + 1];
                const float x10 = smx[py + kh + 1][px + kw];
                const float x11 = smx[py + kh + 1][px + kw + 1];
#pragma unroll
                for (int co = 0; co < 8; co++) {
                    const float wv = smw[co][kh * 3 + kw];
                    acc[co][0] += wv * x00;
                    acc[co][1] += wv * x01;
                    acc[co][2] += wv * x10;
                    acc[co][3] += wv * x11;
                }
            }
        }
        __syncthreads();
    }

    // write out (+bias), mask 126-boundary
#pragma unroll
    for (int co = 0; co < 8; co++) {
        const float bv = bias[cob + co];
        float* yp = g_y + ((size_t)(b * COUT + cob + co)) * (HO * WO);
#pragma unroll
        for (int dy = 0; dy < 2; dy++) {
#pragma unroll
            for (int dx = 0; dx < 2; dx++) {
                int hh = h0 + py + dy;
                int ww = w0 + px + dx;
                if (hh < HO && ww < WO)
                    yp[hh * WO + ww] = acc[co][dy * 2 + dx] + bv;
            }
        }
    }
}

// ---------------------------------------------------------------------------
// Kernel 2: per-(batch, group) mean / rstd over 16 channels x 126x126
// Grid: 256 blocks (one per (b,g)), 256 threads.
// ---------------------------------------------------------------------------
__global__ __launch_bounds__(256)
void stats_kernel()
{
    const int b = blockIdx.x >> 3;
    const int g = blockIdx.x & 7;
    const float* yp = g_y + ((size_t)(b * COUT + g * CPG)) * (HO * WO);
    const int n = CPG * HO * WO;

    float s = 0.f, ss = 0.f;
    for (int i = threadIdx.x; i < n; i += 256) {
        float v = yp[i];
        s += v;
        ss += v * v;
    }

    __shared__ float shs[256], shss[256];
    shs[threadIdx.x] = s;
    shss[threadIdx.x] = ss;
    __syncthreads();
    for (int off = 128; off > 0; off >>= 1) {
        if (threadIdx.x < off) {
            shs[threadIdx.x]  += shs[threadIdx.x + off];
            shss[threadIdx.x] += shss[threadIdx.x + off];
        }
        __syncthreads();
    }
    if (threadIdx.x == 0) {
        float mean = shs[0] / (float)n;
        float var  = shss[0] / (float)n - mean * mean;
        g_mean[blockIdx.x] = mean;
        g_rstd[blockIdx.x] = rsqrtf(var + EPS);
    }
}

// ---------------------------------------------------------------------------
// Kernel 3: normalize + affine + scale + maxpool 2x2 + clamp -> out
// One thread per pooled output element.
// ---------------------------------------------------------------------------
__global__ __launch_bounds__(256)
void pool_kernel(const float* __restrict__ scale,
                 const float* __restrict__ gamma,
                 const float* __restrict__ beta,
                 float* __restrict__ out,
                 int total)
{
    int idx = blockIdx.x * 256 + threadIdx.x;
    if (idx >= total) return;

    int wo = idx % WP;
    int t  = idx / WP;
    int ho = t % HP;   t /= HP;
    int c  = t % COUT;
    int b  = t / COUT;
    int g  = c / CPG;

    const float mean = g_mean[b * NGRP + g];
    const float rstd = g_rstd[b * NGRP + g];
    // fused affine: out_pre = ((y - mean)*rstd*gamma + beta) * scale = a*y + bb
    const float a  = rstd * gamma[c] * scale[c];
    const float bb = (beta[c] - mean * rstd * gamma[c]) * scale[c];

    const float* yp = g_y + ((size_t)(b * COUT + c)) * (HO * WO)
                          + (2 * ho) * WO + 2 * wo;
    float v0 = a * yp[0]      + bb;
    float v1 = a * yp[1]      + bb;
    float v2 = a * yp[WO]     + bb;
    float v3 = a * yp[WO + 1] + bb;
    float m = fmaxf(fmaxf(v0, v1), fmaxf(v2, v3));
    m = fminf(fmaxf(m, 0.0f), 1.0f);
    out[idx] = m;
}

// ---------------------------------------------------------------------------
extern "C" void kernel_launch(void* const* d_in, const int* in_sizes, int n_in,
                              void* d_out, int out_size)
{
    const float* x     = (const float*)d_in[0];
    const float* W     = (const float*)d_in[1];
    const float* bias  = (const float*)d_in[2];
    const float* scale = (const float*)d_in[3];
    const float* gamma = (const float*)d_in[4];
    const float* beta  = (const float*)d_in[5];
    float* out = (float*)d_out;

    // Conv: 4x4 spatial tiles of 32, z = batch(32) * cout-blocks(16)
    dim3 cgrid(4, 4, BATCH * (COUT / 8));
    conv_kernel<<<cgrid, 256>>>(x, W, bias);

    stats_kernel<<<BATCH * NGRP, 256>>>();

    const int total = BATCH * COUT * HP * WP;
    pool_kernel<<<(total + 255) / 256, 256>>>(scale, gamma, beta, out, total);
}

// round 4
// speedup vs baseline: 4.7863x; 4.7863x over previous
#include <cuda_runtime.h>
#include <cstdint>

// ---------------- problem shape ----------------
#define BATCH 32
#define CIN   64
#define HIN   128
#define WIN   128
#define COUT  128
#define HO    126
#define WO    126
#define NGRP  8
#define HP    63
#define WP    63
#define EPS   1e-5f

// ---------------- scratch (static device globals) ----------------
__device__ float g_y[(size_t)BATCH * COUT * HO * WO];   // conv output
__device__ float g_wA[72 * 8 * 32 * 4];                 // W in mma-fragment layout (tf32 bits)
__device__ float g_sum[BATCH * NGRP];
__device__ float g_sumsq[BATCH * NGRP];
__device__ float g_mean[BATCH * NGRP];
__device__ float g_rstd[BATCH * NGRP];

static __device__ __forceinline__ uint32_t f2tf32(float v) {
    uint32_t t;
    asm("cvt.rna.tf32.f32 %0, %1;" : "=r"(t) : "f"(v));
    return t;
}

static __device__ __forceinline__ void mma_tf32(
    float* c, uint32_t a0, uint32_t a1, uint32_t a2, uint32_t a3,
    uint32_t b0, uint32_t b1)
{
    asm volatile(
        "mma.sync.aligned.m16n8k8.row.col.f32.tf32.tf32.f32 "
        "{%0,%1,%2,%3}, {%4,%5,%6,%7}, {%8,%9}, {%0,%1,%2,%3};"
        : "+f"(c[0]), "+f"(c[1]), "+f"(c[2]), "+f"(c[3])
        : "r"(a0), "r"(a1), "r"(a2), "r"(a3), "r"(b0), "r"(b1));
}

// ---------------- kernel 0: pack W into fragment layout + zero sums ------------
// Layout: g_wA[((kchunk*8 + mt)*32 + lane)*4 + j]
//   kchunk = cg*18 + tap*2 + ci8   (cg: 16-ci stage, tap = kh*3+kw, ci8: 8-ci half)
//   j=0: (r, kk=lane%4)  j=1: (r+8, kk)  j=2: (r, kk+4)  j=3: (r+8, kk+4)
//   cout = mt*16 + r (r = lane/4),  ci = cg*16 + ci8*8 + kk
__global__ __launch_bounds__(256)
void pack_kernel(const float* __restrict__ W)
{
    int idx = blockIdx.x * 256 + threadIdx.x;        // 73728 total
    if (idx < BATCH * NGRP) { g_sum[idx] = 0.f; g_sumsq[idx] = 0.f; }
    if (idx >= 72 * 8 * 32 * 4) return;
    int j      = idx & 3;
    int lane   = (idx >> 2) & 31;
    int mt     = (idx >> 7) & 7;
    int kchunk = idx >> 10;
    int cg  = kchunk / 18;
    int t2  = kchunk % 18;
    int tap = t2 >> 1;
    int ci8 = t2 & 1;
    int kk = (lane & 3) + ((j >= 2) ? 4 : 0);
    int r  = (lane >> 2) + ((j & 1) ? 8 : 0);
    int cout = mt * 16 + r;
    int ci   = cg * 16 + ci8 * 8 + kk;
    int kh = tap / 3, kw = tap % 3;
    float v = W[((cout * CIN + ci) * 3 + kh) * 3 + kw];
    ((uint32_t*)g_wA)[idx] = f2tf32(v);
}

// ---------------- kernel 1: implicit-GEMM conv via mma.sync tf32 ------------
// Grid: (HO=126, BATCH=32). CTA: 128 couts x 128 pixels (one output row).
// 8 warps = 2(M) x 4(N); warp tile 64x32.
__global__ __launch_bounds__(256, 2)
void conv_mma_kernel(const float* __restrict__ x,
                     const float* __restrict__ bias)
{
    __shared__ uint32_t xs[16 * 3 * 136];   // tf32 bits, [ci][row][col(136)]

    const int tid  = threadIdx.x;
    const int wid  = tid >> 5;
    const int lane = tid & 31;
    const int warp_m = wid >> 2;            // 0..1
    const int warp_n = wid & 3;             // 0..3
    const int ho = blockIdx.x;
    const int b  = blockIdx.y;

    float acc[4][4][4];
#pragma unroll
    for (int i = 0; i < 4; i++)
#pragma unroll
        for (int n = 0; n < 4; n++)
#pragma unroll
            for (int k = 0; k < 4; k++) acc[i][n][k] = 0.f;

    const int lq = lane & 3;    // quad col
    const int lr = lane >> 2;   // quad row

    for (int cg = 0; cg < 4; cg++) {
        __syncthreads();
        // ---- stage x tile: ci in [cg*16, +16), rows ho..ho+2, cols 0..129 ----
        for (int i = tid; i < 16 * 3 * 136; i += 256) {
            int ci  = i / 408;
            int rem = i - ci * 408;
            int rr  = rem / 136;
            int col = rem - rr * 136;
            float v = 0.f;
            if (col < 128)
                v = x[(((size_t)b * CIN + cg * 16 + ci) * HIN + (ho + rr)) * WIN + col];
            xs[i] = f2tf32(v);
        }
        __syncthreads();

#pragma unroll
        for (int tap = 0; tap < 9; tap++) {
            const int kh = tap / 3, kw = tap % 3;
#pragma unroll
            for (int ci8 = 0; ci8 < 2; ci8++) {
                const int kchunk = cg * 18 + tap * 2 + ci8;
                // A fragments: one float4 per m-tile
                uint32_t a[4][4];
#pragma unroll
                for (int i = 0; i < 4; i++) {
                    float4 f = __ldg(&reinterpret_cast<const float4*>(g_wA)[
                        (kchunk * 8 + warp_m * 4 + i) * 32 + lane]);
                    a[i][0] = __float_as_uint(f.x);
                    a[i][1] = __float_as_uint(f.y);
                    a[i][2] = __float_as_uint(f.z);
                    a[i][3] = __float_as_uint(f.w);
                }
                // B fragments
                uint32_t b0[4], b1[4];
                const int cb = warp_n * 32 + lr + kw;
                const uint32_t* xrow0 = xs + (ci8 * 8 + lq) * 408 + kh * 136;
                const uint32_t* xrow1 = xrow0 + 4 * 408;
#pragma unroll
                for (int nt = 0; nt < 4; nt++) {
                    b0[nt] = xrow0[cb + nt * 8];
                    b1[nt] = xrow1[cb + nt * 8];
                }
#pragma unroll
                for (int i = 0; i < 4; i++)
#pragma unroll
                    for (int nt = 0; nt < 4; nt++)
                        mma_tf32(acc[i][nt], a[i][0], a[i][1], a[i][2], a[i][3],
                                 b0[nt], b1[nt]);
            }
        }
    }

    // ---- epilogue: bias, GN partial sums, store y ----
    float sacc[4], qacc[4];
#pragma unroll
    for (int i = 0; i < 4; i++) { sacc[i] = 0.f; qacc[i] = 0.f; }

    const int coutA = warp_m * 64 + lr;       // + mtl*16 ; rows lr and lr+8
#pragma unroll
    for (int i = 0; i < 4; i++) {
        const int c0 = coutA + i * 16;
        const float bv0 = bias[c0];
        const float bv1 = bias[c0 + 8];
        float* y0 = g_y + (((size_t)b * COUT + c0)     * HO + ho) * WO;
        float* y1 = g_y + (((size_t)b * COUT + c0 + 8) * HO + ho) * WO;
#pragma unroll
        for (int nt = 0; nt < 4; nt++) {
            const int p = warp_n * 32 + nt * 8 + 2 * lq;
            if (p < WO) {
                float v0 = acc[i][nt][0] + bv0;
                float v1 = acc[i][nt][1] + bv0;
                float v2 = acc[i][nt][2] + bv1;
                float v3 = acc[i][nt][3] + bv1;
                sacc[i] += v0 + v1 + v2 + v3;
                qacc[i] += v0 * v0 + v1 * v1 + v2 * v2 + v3 * v3;
                *reinterpret_cast<float2*>(y0 + p) = make_float2(v0, v1);
                *reinterpret_cast<float2*>(y1 + p) = make_float2(v2, v3);
            }
        }
    }
    // warp-reduce and atomic into per-(b,group) sums; group == m-tile index
#pragma unroll
    for (int i = 0; i < 4; i++) {
        float s = sacc[i], q = qacc[i];
#pragma unroll
        for (int off = 16; off > 0; off >>= 1) {
            s += __shfl_xor_sync(0xFFFFFFFF, s, off);
            q += __shfl_xor_sync(0xFFFFFFFF, q, off);
        }
        if (lane == 0) {
            const int g = warp_m * 4 + i;
            atomicAdd(&g_sum[b * NGRP + g], s);
            atomicAdd(&g_sumsq[b * NGRP + g], q);
        }
    }
}

// ---------------- kernel 2: finalize stats ----------------
__global__ void stats_final_kernel()
{
    int t = threadIdx.x;
    if (t < BATCH * NGRP) {
        const float n = (float)((COUT / NGRP) * HO * WO);
        float m = g_sum[t] / n;
        float var = g_sumsq[t] / n - m * m;
        g_mean[t] = m;
        g_rstd[t] = rsqrtf(var + EPS);
    }
}

// ---------------- kernel 3: normalize + affine + scale + pool + clamp --------
__global__ __launch_bounds__(256)
void pool_kernel(const float* __restrict__ scale,
                 const float* __restrict__ gamma,
                 const float* __restrict__ beta,
                 float* __restrict__ out,
                 int total)
{
    int idx = blockIdx.x * 256 + threadIdx.x;
    if (idx >= total) return;

    int wo = idx % WP;
    int t  = idx / WP;
    int ho = t % HP;   t /= HP;
    int c  = t % COUT;
    int b  = t / COUT;
    int g  = c / (COUT / NGRP);

    const float mean = g_mean[b * NGRP + g];
    const float rstd = g_rstd[b * NGRP + g];
    const float a  = rstd * gamma[c] * scale[c];
    const float bb = (beta[c] - mean * rstd * gamma[c]) * scale[c];

    const float* yp = g_y + ((size_t)(b * COUT + c)) * (HO * WO)
                          + (2 * ho) * WO + 2 * wo;
    float v0 = a * yp[0]      + bb;
    float v1 = a * yp[1]      + bb;
    float v2 = a * yp[WO]     + bb;
    float v3 = a * yp[WO + 1] + bb;
    float m = fmaxf(fmaxf(v0, v1), fmaxf(v2, v3));
    m = fminf(fmaxf(m, 0.0f), 1.0f);
    out[idx] = m;
}

// ---------------- host launcher ----------------
extern "C" void kernel_launch(void* const* d_in, const int* in_sizes, int n_in,
                              void* d_out, int out_size)
{
    const float* x     = (const float*)d_in[0];
    const float* W     = (const float*)d_in[1];
    const float* bias  = (const float*)d_in[2];
    const float* scale = (const float*)d_in[3];
    const float* gamma = (const float*)d_in[4];
    const float* beta  = (const float*)d_in[5];
    float* out = (float*)d_out;

    pack_kernel<<<288, 256>>>(W);

    dim3 cgrid(HO, BATCH);       // 126 x 32
    conv_mma_kernel<<<cgrid, 256>>>(x, bias);

    stats_final_kernel<<<1, 256>>>();

    const int total = BATCH * COUT * HP * WP;
    pool_kernel<<<(total + 255) / 256, 256>>>(scale, gamma, beta, out, total);
}

// round 5
// speedup vs baseline: 6.5867x; 1.3762x over previous
#include <cuda_runtime.h>
#include <cstdint>

// ---------------- problem shape ----------------
#define BATCH 32
#define CIN   64
#define HIN   128
#define WIN   128
#define COUT  128
#define HO    126
#define WO    126
#define NGRP  8
#define HP    63
#define WP    63
#define EPS   1e-5f

#define XS_STRIDE 408            // 3*136 per ci
#define XS_ELEMS  (16 * 3 * 136) // 6528 per buffer

// ---------------- scratch (static device globals) ----------------
__device__ float g_y[(size_t)BATCH * COUT * HO * WO];   // conv output
__device__ float g_wA[72 * 8 * 32 * 4];                 // W in mma-fragment layout (tf32 bits)
__device__ float g_sum[BATCH * NGRP];
__device__ float g_sumsq[BATCH * NGRP];
__device__ float g_mean[BATCH * NGRP];
__device__ float g_rstd[BATCH * NGRP];

static __device__ __forceinline__ uint32_t f2tf32(float v) {
    uint32_t t;
    asm("cvt.rna.tf32.f32 %0, %1;" : "=r"(t) : "f"(v));
    return t;
}

static __device__ __forceinline__ void mma_tf32(
    float* c, uint32_t a0, uint32_t a1, uint32_t a2, uint32_t a3,
    uint32_t b0, uint32_t b1)
{
    asm volatile(
        "mma.sync.aligned.m16n8k8.row.col.f32.tf32.tf32.f32 "
        "{%0,%1,%2,%3}, {%4,%5,%6,%7}, {%8,%9}, {%0,%1,%2,%3};"
        : "+f"(c[0]), "+f"(c[1]), "+f"(c[2]), "+f"(c[3])
        : "r"(a0), "r"(a1), "r"(a2), "r"(a3), "r"(b0), "r"(b1));
}

static __device__ __forceinline__ void cp_async16(uint32_t dst_smem, const void* src) {
    asm volatile("cp.async.ca.shared.global [%0], [%1], 16;"
                 :: "r"(dst_smem), "l"(src) : "memory");
}
static __device__ __forceinline__ void cp_commit() {
    asm volatile("cp.async.commit_group;" ::: "memory");
}
template <int N>
static __device__ __forceinline__ void cp_wait() {
    asm volatile("cp.async.wait_group %0;" :: "n"(N) : "memory");
}
static __device__ __forceinline__ uint32_t smem_u32(const void* p) {
    uint32_t a;
    asm("{ .reg .u64 t; cvta.to.shared.u64 t, %1; cvt.u32.u64 %0, t; }"
        : "=r"(a) : "l"(p));
    return a;
}

// ---------------- kernel 0: pack W into fragment layout + zero sums ------------
// g_wA[((kchunk*8 + mt)*32 + lane)*4 + j]
//   kchunk = cg*18 + tap*2 + ci8; j=0:(r,kk) j=1:(r+8,kk) j=2:(r,kk+4) j=3:(r+8,kk+4)
//   cout = mt*16 + r (r=lane/4), ci = cg*16 + ci8*8 + kk (kk=lane%4 [+4])
__global__ __launch_bounds__(256)
void pack_kernel(const float* __restrict__ W)
{
    int idx = blockIdx.x * 256 + threadIdx.x;        // 73728 total
    if (idx < BATCH * NGRP) { g_sum[idx] = 0.f; g_sumsq[idx] = 0.f; }
    if (idx >= 72 * 8 * 32 * 4) return;
    int j      = idx & 3;
    int lane   = (idx >> 2) & 31;
    int mt     = (idx >> 7) & 7;
    int kchunk = idx >> 10;
    int cg  = kchunk / 18;
    int t2  = kchunk % 18;
    int tap = t2 >> 1;
    int ci8 = t2 & 1;
    int kk = (lane & 3) + ((j >= 2) ? 4 : 0);
    int r  = (lane >> 2) + ((j & 1) ? 8 : 0);
    int cout = mt * 16 + r;
    int ci   = cg * 16 + ci8 * 8 + kk;
    int kh = tap / 3, kw = tap % 3;
    float v = W[((cout * CIN + ci) * 3 + kh) * 3 + kw];
    ((uint32_t*)g_wA)[idx] = f2tf32(v);
}

// ---------------- kernel 1: implicit-GEMM conv, cp.async double-buffered ------
// Grid: (HO, BATCH). CTA: 128 couts x 128 pixels (one output row). 8 warps 2Mx4N.
__global__ __launch_bounds__(256, 2)
void conv_mma_kernel(const float* __restrict__ x,
                     const float* __restrict__ bias)
{
    extern __shared__ uint32_t xs[];   // [2][XS_ELEMS] raw f32 bits (tf32 by truncation)
    const uint32_t xs_base = smem_u32(xs);

    const int tid  = threadIdx.x;
    const int wid  = tid >> 5;
    const int lane = tid & 31;
    const int warp_m = wid >> 2;            // 0..1
    const int warp_n = wid & 3;             // 0..3
    const int ho = blockIdx.x;
    const int b  = blockIdx.y;

    // pre-zero pad cols 128..135 in both buffers (96 rows, 2 float4 each)
    for (int i = tid; i < 2 * 16 * 3; i += 256) {
        int buf = i >= 48;
        int row = i - buf * 48;                       // ci*3 + rr
        float4* p = reinterpret_cast<float4*>(xs + buf * XS_ELEMS + row * 136 + 128);
        p[0] = make_float4(0.f, 0.f, 0.f, 0.f);
        // 136-128 = 8 floats = 2 float4
        p[1] = make_float4(0.f, 0.f, 0.f, 0.f);
    }
    __syncthreads();

    // stage helper: cg chunk -> buffer (cg&1); 1536 float4, 6 per thread
    auto stage = [&](int cg) {
        const uint32_t dstb = xs_base + (cg & 1) * (XS_ELEMS * 4);
        const float* src_base = x + (((size_t)b * CIN + cg * 16) * HIN + ho) * WIN;
#pragma unroll
        for (int k = 0; k < 6; k++) {
            int c = tid + 256 * k;          // 0..1535
            int ci  = c / 96;
            int rem = c - ci * 96;
            int rr  = rem >> 5;
            int q   = rem & 31;
            cp_async16(dstb + (uint32_t)(ci * XS_STRIDE + rr * 136 + q * 4) * 4,
                       src_base + (size_t)ci * (HIN * WIN) + rr * WIN + q * 4);
        }
        cp_commit();
    };

    float acc[4][4][4];
#pragma unroll
    for (int i = 0; i < 4; i++)
#pragma unroll
        for (int n = 0; n < 4; n++)
#pragma unroll
            for (int k = 0; k < 4; k++) acc[i][n][k] = 0.f;

    const int lq = lane & 3;    // quad col -> k index
    const int lr = lane >> 2;   // quad row -> n index

    stage(0);

    for (int cg = 0; cg < 4; cg++) {
        if (cg + 1 < 4) stage(cg + 1);
        if (cg + 1 < 4) cp_wait<1>(); else cp_wait<0>();
        __syncthreads();

        const uint32_t* xbuf = xs + (cg & 1) * XS_ELEMS;

#pragma unroll
        for (int tap = 0; tap < 9; tap++) {
            const int kh = tap / 3, kw = tap % 3;
#pragma unroll
            for (int ci8 = 0; ci8 < 2; ci8++) {
                const int kchunk = cg * 18 + tap * 2 + ci8;
                uint32_t a[4][4];
#pragma unroll
                for (int i = 0; i < 4; i++) {
                    float4 f = __ldg(&reinterpret_cast<const float4*>(g_wA)[
                        (kchunk * 8 + warp_m * 4 + i) * 32 + lane]);
                    a[i][0] = __float_as_uint(f.x);
                    a[i][1] = __float_as_uint(f.y);
                    a[i][2] = __float_as_uint(f.z);
                    a[i][3] = __float_as_uint(f.w);
                }
                uint32_t b0[4], b1[4];
                const int cb = warp_n * 32 + lr + kw;
                const uint32_t* xrow0 = xbuf + (ci8 * 8 + lq) * XS_STRIDE + kh * 136;
                const uint32_t* xrow1 = xrow0 + 4 * XS_STRIDE;
#pragma unroll
                for (int nt = 0; nt < 4; nt++) {
                    b0[nt] = xrow0[cb + nt * 8];
                    b1[nt] = xrow1[cb + nt * 8];
                }
#pragma unroll
                for (int i = 0; i < 4; i++)
#pragma unroll
                    for (int nt = 0; nt < 4; nt++)
                        mma_tf32(acc[i][nt], a[i][0], a[i][1], a[i][2], a[i][3],
                                 b0[nt], b1[nt]);
            }
        }
        __syncthreads();   // protect buffer reuse by next stage
    }

    // ---- epilogue: bias, GN partial sums, store y ----
    float sacc[4], qacc[4];
#pragma unroll
    for (int i = 0; i < 4; i++) { sacc[i] = 0.f; qacc[i] = 0.f; }

    const int coutA = warp_m * 64 + lr;
#pragma unroll
    for (int i = 0; i < 4; i++) {
        const int c0 = coutA + i * 16;
        const float bv0 = bias[c0];
        const float bv1 = bias[c0 + 8];
        float* y0 = g_y + (((size_t)b * COUT + c0)     * HO + ho) * WO;
        float* y1 = g_y + (((size_t)b * COUT + c0 + 8) * HO + ho) * WO;
#pragma unroll
        for (int nt = 0; nt < 4; nt++) {
            const int p = warp_n * 32 + nt * 8 + 2 * lq;
            if (p < WO) {
                float v0 = acc[i][nt][0] + bv0;
                float v1 = acc[i][nt][1] + bv0;
                float v2 = acc[i][nt][2] + bv1;
                float v3 = acc[i][nt][3] + bv1;
                sacc[i] += v0 + v1 + v2 + v3;
                qacc[i] += v0 * v0 + v1 * v1 + v2 * v2 + v3 * v3;
                *reinterpret_cast<float2*>(y0 + p) = make_float2(v0, v1);
                *reinterpret_cast<float2*>(y1 + p) = make_float2(v2, v3);
            }
        }
    }
#pragma unroll
    for (int i = 0; i < 4; i++) {
        float s = sacc[i], q = qacc[i];
#pragma unroll
        for (int off = 16; off > 0; off >>= 1) {
            s += __shfl_xor_sync(0xFFFFFFFF, s, off);
            q += __shfl_xor_sync(0xFFFFFFFF, q, off);
        }
        if (lane == 0) {
            const int g = warp_m * 4 + i;
            atomicAdd(&g_sum[b * NGRP + g], s);
            atomicAdd(&g_sumsq[b * NGRP + g], q);
        }
    }
}

// ---------------- kernel 2: finalize stats ----------------
__global__ void stats_final_kernel()
{
    int t = threadIdx.x;
    if (t < BATCH * NGRP) {
        const float n = (float)((COUT / NGRP) * HO * WO);
        float m = g_sum[t] / n;
        float var = g_sumsq[t] / n - m * m;
        g_mean[t] = m;
        g_rstd[t] = rsqrtf(var + EPS);
    }
}

// ---------------- kernel 3: normalize + affine + scale + pool + clamp --------
__global__ __launch_bounds__(256)
void pool_kernel(const float* __restrict__ scale,
                 const float* __restrict__ gamma,
                 const float* __restrict__ beta,
                 float* __restrict__ out,
                 int total)
{
    int idx = blockIdx.x * 256 + threadIdx.x;
    if (idx >= total) return;

    int wo = idx % WP;
    int t  = idx / WP;
    int ho = t % HP;   t /= HP;
    int c  = t % COUT;
    int b  = t / COUT;
    int g  = c / (COUT / NGRP);

    const float mean = g_mean[b * NGRP + g];
    const float rstd = g_rstd[b * NGRP + g];
    const float a  = rstd * gamma[c] * scale[c];
    const float bb = (beta[c] - mean * rstd * gamma[c]) * scale[c];

    const float* yp = g_y + ((size_t)(b * COUT + c)) * (HO * WO)
                          + (2 * ho) * WO + 2 * wo;
    float2 p01 = __ldcs(reinterpret_cast<const float2*>(yp));
    float2 p23 = __ldcs(reinterpret_cast<const float2*>(yp + WO));
    float v0 = a * p01.x + bb;
    float v1 = a * p01.y + bb;
    float v2 = a * p23.x + bb;
    float v3 = a * p23.y + bb;
    float m = fmaxf(fmaxf(v0, v1), fmaxf(v2, v3));
    m = fminf(fmaxf(m, 0.0f), 1.0f);
    out[idx] = m;
}

// ---------------- host launcher ----------------
extern "C" void kernel_launch(void* const* d_in, const int* in_sizes, int n_in,
                              void* d_out, int out_size)
{
    const float* x     = (const float*)d_in[0];
    const float* W     = (const float*)d_in[1];
    const float* bias  = (const float*)d_in[2];
    const float* scale = (const float*)d_in[3];
    const float* gamma = (const float*)d_in[4];
    const float* beta  = (const float*)d_in[5];
    float* out = (float*)d_out;

    static int smem_set = 0;
    const int smem_bytes = 2 * XS_ELEMS * 4;   // 52224
    if (!smem_set) {
        cudaFuncSetAttribute(conv_mma_kernel,
                             cudaFuncAttributeMaxDynamicSharedMemorySize, smem_bytes);
        smem_set = 1;
    }

    pack_kernel<<<288, 256>>>(W);

    dim3 cgrid(HO, BATCH);       // 126 x 32
    conv_mma_kernel<<<cgrid, 256, smem_bytes>>>(x, bias);

    stats_final_kernel<<<1, 256>>>();

    const int total = BATCH * COUT * HP * WP;
    pool_kernel<<<(total + 255) / 256, 256>>>(scale, gamma, beta, out, total);
}